// round 6
// baseline (speedup 1.0000x reference)
#include <cuda_runtime.h>

#define NTOT 131072
typedef unsigned long long ull;

// ---------- f32x2 helpers ----------
__device__ __forceinline__ ull dup2(float a) {
    ull r; asm("mov.b64 %0, {%1, %1};" : "=l"(r) : "f"(a)); return r;
}
__device__ __forceinline__ ull ffma2(ull a, ull b, ull c) {
    ull d; asm("fma.rn.f32x2 %0, %1, %2, %3;" : "=l"(d) : "l"(a), "l"(b), "l"(c)); return d;
}
__device__ __forceinline__ ull fadd2(ull a, ull b) {
    ull d; asm("add.rn.f32x2 %0, %1, %2;" : "=l"(d) : "l"(a), "l"(b)); return d;
}
__device__ __forceinline__ void f2unpack(float& lo, float& hi, ull v) {
    asm("mov.b64 {%0, %1}, %2;" : "=f"(lo), "=f"(hi) : "l"(v));
}

// ---------- scratch ----------
__device__ float4 g_xT4[NTOT * 32 / 4];
__device__ float4 g_t4[8515584 / 4];
#define g_xT ((float*)g_xT4)
#define g_t  ((float*)g_t4)

// ranks and t-offsets (t layout: [block][r][n], n fastest, 32 wide)
__constant__ int c_R[12]    = {64,64,64,64,64,64,64,64,64,52,32,20};
__constant__ int c_TOFF[12] = {0,4096,12288,28672,61440,126976,258048,520192,
                               1044480,2093056,3796992,5894144};
#define H_TOFF9 2093056          // zero region end (levels 0-8 atomic)

struct P { const float* u[12]; };

// ---------- transpose x: [B][N] -> [N][B] ----------
__global__ void k_transpose_in(const float* __restrict__ x) {
    __shared__ float tile[32][33];
    int i0 = blockIdx.x * 32;
    int tx = threadIdx.x, ty = threadIdx.y;
    tile[ty][tx] = x[(size_t)ty * NTOT + i0 + tx];
    __syncthreads();
    g_xT[(size_t)(i0 + ty) * 32 + tx] = tile[tx][ty];
}

__global__ void k_zero_t() {
    int i = blockIdx.x * blockDim.x + threadIdx.x;
    if (i < H_TOFF9 / 4) g_t4[i] = make_float4(0.f, 0.f, 0.f, 0.f);
}

// ---------- core 16-FFMA2 step: acc[j][c] += dup(a8[j]) * b2[c] ----------
__device__ __forceinline__ void step16(const float* __restrict__ a8,
                                       const ull* __restrict__ b2, ull* __restrict__ acc) {
    float4 A0 = *(const float4*)a8;
    float4 A1 = *(const float4*)(a8 + 4);
    ulonglong2 B = *(const ulonglong2*)b2;
    float av[8] = {A0.x, A0.y, A0.z, A0.w, A1.x, A1.y, A1.z, A1.w};
    #pragma unroll
    for (int j = 0; j < 8; j++) {
        ull ad = dup2(av[j]);
        acc[2*j]   = ffma2(ad, B.x, acc[2*j]);
        acc[2*j+1] = ffma2(ad, B.y, acc[2*j+1]);
    }
}

// ================= phase 1: t[block][r][n] = sum_s U[s][r] x[s][n] =================
// CTA = 256 thr (8 warps), slice = 128 s. Warp tile 32r x 32n, thread tile 8r x 4n.
__global__ void __launch_bounds__(256) k_p1(P p) {
    __shared__ __align__(16) ull  xs2[2048];   // x slice [s128][16 ull]  (16KB)
    __shared__ __align__(16) float us[8192];   // U slice [s128][64] / reduce buf (32KB)
    int tid = threadIdx.x, slice = blockIdx.x;
    int w = tid >> 5, lane = tid & 31, ri = lane >> 3, ni = lane & 7;

    {   // stage x (coalesced, n-pairs natural)
        const float4* src = g_xT4 + (size_t)slice * 1024;
        float4* d = (float4*)xs2;
        for (int i = tid; i < 1024; i += 256) d[i] = src[i];
    }

    #pragma unroll 1
    for (int l = 0; l < 12; l++) {
        int R = c_R[l];
        int rq = R / 4;
        __syncthreads();
        {   // stage U natural [s][64], zero-pad cols >= R
            const float4* u4 = (const float4*)p.u[l] + (size_t)slice * 128 * rq;
            float4* d = (float4*)us;
            for (int i = tid; i < 2048; i += 256) {
                int s = i >> 4, c4 = i & 15;
                d[i] = (c4 < rq) ? u4[s * rq + c4] : make_float4(0.f, 0.f, 0.f, 0.f);
            }
        }
        __syncthreads();

        ull acc[16];
        #pragma unroll
        for (int j = 0; j < 16; j++) acc[j] = 0;

        int sbeg, K, rbase, active = 1;
        if (l <= 9)      { rbase = (w >> 2) * 32; sbeg = (w & 3) * 32;               K = 32; }
        else if (l == 10){ rbase = 0;             sbeg = (w >> 2) * 64 + (w & 3)*16; K = 16; }
        else             { rbase = 0;             sbeg = (w & 3) * 32;               K = 32; active = (w < 4); }

        if (active) {
            #pragma unroll 2
            for (int k = 0; k < K; k++) {
                int s = sbeg + k;
                step16(us + s * 64 + rbase + ri * 8, xs2 + s * 16 + ni * 2, acc);
            }
        }

        if (l == 11) {
            if (w < 4) {   // direct store, block fully inside warp's K
                int block = slice * 4 + w;
                float* td = g_t + c_TOFF[11] + (size_t)block * 20 * 32;
                #pragma unroll
                for (int rr = 0; rr < 8; rr++) {
                    int r = ri * 8 + rr;
                    if (r < 20) {
                        #pragma unroll
                        for (int c = 0; c < 2; c++)
                            *(ull*)(td + r * 32 + ni * 4 + c * 2) = acc[rr * 2 + c];
                    }
                }
            }
        } else {
            __syncthreads();
            ull* red = (ull*)us;
            {
                ull* dst = red + w * 512 + lane * 16;
                #pragma unroll
                for (int j = 0; j < 16; j++) dst[j] = acc[j];
            }
            __syncthreads();
            // 4-way cross-warp reduce + store (1024 ull outputs, 4 per thread)
            #pragma unroll
            for (int q = 0; q < 4; q++) {
                int o = tid * 4 + q;
                int grp, r, n2;
                if (l <= 9) { r = o >> 4;  n2 = o & 15; grp = r >> 5; }
                else        { grp = o >> 9; r = (o >> 4) & 31; n2 = o & 15; }
                int rl = r & 31;
                int idx = ((rl >> 3) * 8 + (n2 >> 1)) * 16 + (rl & 7) * 2 + (n2 & 1);
                ull v = fadd2(fadd2(red[(grp*4+0)*512 + idx], red[(grp*4+1)*512 + idx]),
                              fadd2(red[(grp*4+2)*512 + idx], red[(grp*4+3)*512 + idx]));
                int n = n2 * 2;
                if (l <= 8) {
                    int block = slice >> (9 - l);
                    float* td = g_t + c_TOFF[l] + ((size_t)block * 64 + r) * 32 + n;
                    float lo, hi; f2unpack(lo, hi, v);
                    atomicAdd(td, lo); atomicAdd(td + 1, hi);
                } else if (l == 9) {
                    if (r < 52)
                        *(ull*)(g_t + c_TOFF[9] + ((size_t)slice * 52 + r) * 32 + n) = v;
                } else {  // l == 10
                    int block = slice * 2 + grp;
                    *(ull*)(g_t + c_TOFF[10] + ((size_t)block * 32 + r) * 32 + n) = v;
                }
            }
        }
    }
}

// ================= epilogue: y = leaf + sum_l s2 * U t_sib ; out transpose =================
// CTA = 256 thr (8 warps), slice = 128 s. Warp: s-tile st = w&3 (32 s), K-half kh = w>>2.
// acc (8s x 4n as 16 f32x2) lives in registers across leaf + all 12 levels.
__global__ void __launch_bounds__(256) k_epi(P p, const float* __restrict__ lb,
                                             const float* __restrict__ sc,
                                             float* __restrict__ out) {
    extern __shared__ __align__(16) char smraw[];
    float* ut = (float*)smraw;                 // 8448 fl: U^T [k][132] / lbt / y merge buf
    ull*  B2 = (ull*)(smraw + 33792);          // 2048 ull: xs (leaf) / ts2
    int tid = threadIdx.x, slice = blockIdx.x;
    int w = tid >> 5, lane = tid & 31, si = lane >> 3, ni = lane & 7;
    int st = w & 3, kh = w >> 2;
    int s0l = st * 32;

    {   // stage leaf blocks transposed: lbt[q][s][t], stride 36
        const float4* lb4 = (const float4*)lb + (size_t)slice * 1024;
        for (int i = tid; i < 1024; i += 256) {
            int q = i >> 8, t = (i >> 3) & 31, s4 = i & 7;
            float4 v = lb4[i];
            float* dst = ut + q * 1152 + (s4 * 4) * 36 + t;
            dst[0] = v.x; dst[36] = v.y; dst[72] = v.z; dst[108] = v.w;
        }
        const float4* xsrc = g_xT4 + (size_t)slice * 1024;
        float4* xd = (float4*)B2;
        for (int i = tid; i < 1024; i += 256) xd[i] = xsrc[i];
    }
    __syncthreads();

    ull acc[16];
    #pragma unroll
    for (int j = 0; j < 16; j++) acc[j] = 0;

    // leaf: y[t][n] = sum_s lb[t][s] x[s][n]; K split in halves of 16
    for (int k = kh * 16; k < kh * 16 + 16; k++)
        step16(ut + st * 1152 + k * 36 + si * 8, B2 + (st * 32 + k) * 16 + ni * 2, acc);

    float scv = __ldg(sc);
    float s2 = scv * scv;

    #pragma unroll 1
    for (int l = 0; l < 12; l++) {
        int R = c_R[l];
        int rq = R / 4;
        __syncthreads();
        {   // stage U transposed: ut[k][s], stride 132 (coalesced read, scatter write)
            const float4* u4 = (const float4*)p.u[l] + (size_t)slice * 128 * rq;
            for (int i = tid; i < 2048; i += 256) {
                int s = i >> 4, c4 = i & 15;
                if (c4 < rq) {
                    float4 v = u4[s * rq + c4];
                    float* dst = ut + (c4 * 4) * 132 + s;
                    dst[0] = v.x; dst[132] = v.y; dst[264] = v.z; dst[396] = v.w;
                }
            }
            // stage sibling t, scaled by s2, n-pair packed: ts2[(sib)][k][16 ull]
            const float4* tsrc; int nf4;
            if (l <= 8)      { int sib = (slice >> (9 - l)) ^ 1;
                               tsrc = (const float4*)(g_t + c_TOFF[l]) + (size_t)sib * 512; nf4 = 512; }
            else if (l == 9) { int sib = slice ^ 1;
                               tsrc = (const float4*)(g_t + c_TOFF[9]) + (size_t)sib * 416; nf4 = 416; }
            else if (l == 10){ tsrc = (const float4*)(g_t + c_TOFF[10]) + (size_t)slice * 512; nf4 = 512; }
            else             { tsrc = (const float4*)(g_t + c_TOFF[11]) + (size_t)slice * 640; nf4 = 640; }
            float4* td = (float4*)B2;
            for (int i = tid; i < nf4; i += 256) {
                float4 v = tsrc[i];
                v.x *= s2; v.y *= s2; v.z *= s2; v.w *= s2;
                td[i] = v;
            }
        }
        __syncthreads();

        int tsb = 0;
        if (l == 10)      tsb = ((st >> 1) ^ 1) * (32 * 16);
        else if (l == 11) tsb = (st ^ 1) * (20 * 16);

        int Kh = R / 2;
        int k0 = kh * Kh, k1 = k0 + Kh;
        for (int k = k0; k < k1; k++)
            step16(ut + k * 132 + s0l + si * 8, B2 + tsb + k * 16 + ni * 2, acc);
    }

    // ---- merge K-halves in one buffer (ut region, stride 34: 4352 <= 8448 fl) ----
    __syncthreads();
    float* yb = ut;
    if (kh == 1) {
        #pragma unroll
        for (int rr = 0; rr < 8; rr++) {
            int s = s0l + si * 8 + rr;
            #pragma unroll
            for (int c = 0; c < 2; c++)
                *(ull*)(yb + s * 34 + ni * 4 + c * 2) = acc[rr * 2 + c];
        }
    }
    __syncthreads();
    if (kh == 0) {
        #pragma unroll
        for (int rr = 0; rr < 8; rr++) {
            int s = s0l + si * 8 + rr;
            #pragma unroll
            for (int c = 0; c < 2; c++) {
                ull* pp = (ull*)(yb + s * 34 + ni * 4 + c * 2);
                *pp = fadd2(*pp, acc[rr * 2 + c]);
            }
        }
    }
    __syncthreads();
    // transpose-out: out[n][slice*128 + s] = yb[s][n]
    for (int i = tid; i < 4096; i += 256) {
        int n = i >> 7, s = i & 127;
        out[(size_t)n * NTOT + slice * 128 + s] = yb[s * 34 + n];
    }
}

// ---------- driver ----------
extern "C" void kernel_launch(void* const* d_in, const int* in_sizes, int n_in,
                              void* d_out, int out_size) {
    (void)in_sizes; (void)n_in; (void)out_size;
    const float* x  = (const float*)d_in[0];
    const float* lb = (const float*)d_in[1];
    const float* sc = (const float*)d_in[2];
    P p;
    for (int l = 0; l < 12; l++) p.u[l] = (const float*)d_in[3 + l];
    float* out = (float*)d_out;

    const int SMEM_EPI = 33792 + 16384;   // 50176 B
    cudaFuncSetAttribute(k_epi, cudaFuncAttributeMaxDynamicSharedMemorySize, SMEM_EPI);

    k_transpose_in<<<4096, dim3(32, 32)>>>(x);
    k_zero_t<<<(H_TOFF9 / 4 + 255) / 256, 256>>>();
    k_p1<<<1024, 256>>>(p);
    k_epi<<<1024, 256, SMEM_EPI>>>(p, lb, sc, out);
}